// round 3
// baseline (speedup 1.0000x reference)
#include <cuda_runtime.h>
#include <cstdint>

// ---------------------------------------------------------------------------
// GlobalPropagation: 3-hop symmetric-normalized graph propagation (GCN-style)
//   deg[i]   = 1 + #edges with row==i           (self loop appended)
//   dinv[i]  = rsqrt(deg[i])
//   w_e      = dinv[row_e] * dinv[col_e]
//   H^{k+1}[i] = sum_{e: row_e==i} w_e * H^k[col_e]     (x3)
//
// CSR built once per launch (counting sort by row), then 3 atomic-free
// warp-per-row gather SpMM hops. H (51 MB) fits in L2 -> hops are L2-BW-bound.
//
// edge_list dtype is sniffed ON DEVICE (int64 vs int32): JAX without x64
// silently downcasts jnp.int64 -> int32. int64 little-endian view of small
// values is [val,0,val,0,...], so "odd int32 words all zero" <=> int64.
// ---------------------------------------------------------------------------

#define FEAT 128                 // feature dim (float4 x 32 lanes)
#define N_MAX 131072             // >= 100000 nodes
#define E_MAX 3400000            // >= 3200000 edges
#define CSR_MAX (E_MAX + N_MAX)  // edges + self loops
#define SCAN_B 1024

// Scratch (allocation-free rule: __device__ globals)
__device__ int   g_is64;
__device__ int   g_deg[N_MAX];
__device__ int   g_off[N_MAX + 1];
__device__ int   g_cur[N_MAX];
__device__ float g_dinv[N_MAX];
__device__ int   g_col[CSR_MAX];
__device__ float g_w[CSR_MAX];
__device__ int   g_bsum[(N_MAX + SCAN_B - 1) / SCAN_B];
__device__ float g_bufA[(size_t)N_MAX * FEAT];
__device__ float g_bufB[(size_t)N_MAX * FEAT];

// ---------------------------------------------------------------------------
// 0) dtype sniffer: odd int32 words of first 8 elements all zero => int64
__global__ void k_detect(const unsigned int* __restrict__ p) {
    if (threadIdx.x == 0 && blockIdx.x == 0) {
        bool is64 = true;
        #pragma unroll
        for (int i = 1; i < 16; i += 2) is64 = is64 && (p[i] == 0u);
        g_is64 = is64 ? 1 : 0;
    }
}

__device__ __forceinline__ int load_edge(const void* base, long long idx) {
    if (g_is64) return (int)((const long long*)base)[idx];
    return ((const int*)base)[idx];
}

// 1) degree init (self loop contributes 1)
__global__ void k_deg_init(int n) {
    int i = blockIdx.x * blockDim.x + threadIdx.x;
    if (i < n) g_deg[i] = 1;
}

// 2) histogram of row indices (rows = elements [0, e))
__global__ void k_deg_hist(const void* __restrict__ edges, int e) {
    int i = blockIdx.x * blockDim.x + threadIdx.x;
    if (i < e) atomicAdd(&g_deg[load_edge(edges, i)], 1);
}

// 3) block-local exclusive scan of g_deg -> g_off, block totals -> g_bsum
__global__ void k_scan1(int n) {
    __shared__ int sh[SCAN_B];
    int i = blockIdx.x * SCAN_B + threadIdx.x;
    int v = (i < n) ? g_deg[i] : 0;
    sh[threadIdx.x] = v;
    __syncthreads();
    #pragma unroll
    for (int off = 1; off < SCAN_B; off <<= 1) {
        int t = (threadIdx.x >= off) ? sh[threadIdx.x - off] : 0;
        __syncthreads();
        sh[threadIdx.x] += t;
        __syncthreads();
    }
    if (i < n) g_off[i] = sh[threadIdx.x] - v;     // exclusive within block
    if (threadIdx.x == SCAN_B - 1) g_bsum[blockIdx.x] = sh[SCAN_B - 1];
}

// 4) exclusive scan of the (<=1024) block sums, single block
__global__ void k_scan2(int nb) {
    __shared__ int sh[SCAN_B];
    int v = (threadIdx.x < nb) ? g_bsum[threadIdx.x] : 0;
    sh[threadIdx.x] = v;
    __syncthreads();
    #pragma unroll
    for (int off = 1; off < SCAN_B; off <<= 1) {
        int t = (threadIdx.x >= off) ? sh[threadIdx.x - off] : 0;
        __syncthreads();
        sh[threadIdx.x] += t;
        __syncthreads();
    }
    if (threadIdx.x < nb) g_bsum[threadIdx.x] = sh[threadIdx.x] - v;
}

// 5) add block offsets, init cursors, dinv, and tail sentinel
__global__ void k_scan3(int n, int total) {
    int i = blockIdx.x * blockDim.x + threadIdx.x;
    if (i < n) {
        int o = g_off[i] + g_bsum[i / SCAN_B];
        g_off[i] = o;
        g_cur[i] = o;
        g_dinv[i] = rsqrtf((float)g_deg[i]);
    }
    if (i == 0) g_off[n] = total;
}

// 6) scatter edges + self loops into CSR slots (w precomputed)
//    rows = elements [0, e), cols = elements [e, 2e)
__global__ void k_fill(const void* __restrict__ edges, int e, int n) {
    int i = blockIdx.x * blockDim.x + threadIdx.x;
    if (i < e) {
        int r = load_edge(edges, i);
        int c = load_edge(edges, (long long)e + i);
        int p = atomicAdd(&g_cur[r], 1);
        g_col[p] = c;
        g_w[p]   = g_dinv[r] * g_dinv[c];
    } else if (i < e + n) {
        int r = i - e;                 // self loop
        int p = atomicAdd(&g_cur[r], 1);
        g_col[p] = r;
        float d = g_dinv[r];
        g_w[p]   = d * d;
    }
}

// 7) warp-per-row gather SpMM: out[r] = sum_j w_j * Hin[col_j]
//    32 lanes x float4 = one full 512B coalesced row per neighbor, no atomics.
//    SRC/DST: 0 = external pointer param, 1 = g_bufA, 2 = g_bufB
template <int SRC, int DST>
__global__ void __launch_bounds__(256)
k_spmm(const float* __restrict__ Hext, float* __restrict__ Oext, int n) {
    const float* __restrict__ Hin =
        (SRC == 0) ? Hext : (SRC == 1 ? (const float*)g_bufA : (const float*)g_bufB);
    float* __restrict__ Hout =
        (DST == 0) ? Oext : (DST == 1 ? g_bufA : g_bufB);

    int warp = (blockIdx.x * blockDim.x + threadIdx.x) >> 5;
    int lane = threadIdx.x & 31;
    if (warp >= n) return;

    int start = g_off[warp];
    int end   = g_off[warp + 1];

    float4 acc = make_float4(0.f, 0.f, 0.f, 0.f);

    for (int base = start; base < end; base += 32) {
        int idx = base + lane;
        int   c = 0;
        float w = 0.f;
        if (idx < end) { c = g_col[idx]; w = g_w[idx]; }
        int cnt = end - base;
        if (cnt > 32) cnt = 32;
        #pragma unroll 8
        for (int j = 0; j < cnt; ++j) {
            int   cj = __shfl_sync(0xffffffffu, c, j);
            float wj = __shfl_sync(0xffffffffu, w, j);
            float4 h = __ldg(((const float4*)(Hin + (size_t)cj * FEAT)) + lane);
            acc.x = fmaf(wj, h.x, acc.x);
            acc.y = fmaf(wj, h.y, acc.y);
            acc.z = fmaf(wj, h.z, acc.z);
            acc.w = fmaf(wj, h.w, acc.w);
        }
    }
    ((float4*)(Hout + (size_t)warp * FEAT))[lane] = acc;
}

// ---------------------------------------------------------------------------
extern "C" void kernel_launch(void* const* d_in, const int* in_sizes, int n_in,
                              void* d_out, int out_size) {
    const float* h_local = (const float*)d_in[0];
    const void*  edges   = d_in[1];

    int n = in_sizes[0] / FEAT;     // number of nodes (100000)
    int e = in_sizes[1] / 2;        // number of edges (3200000)

    const int T = 256;
    int nb_n  = (n + T - 1) / T;
    int nb_e  = (e + T - 1) / T;
    int nb_en = (e + n + T - 1) / T;
    int nb_sc = (n + SCAN_B - 1) / SCAN_B;

    // --- dtype sniff + CSR build ---
    k_detect<<<1, 32>>>((const unsigned int*)edges);
    k_deg_init<<<nb_n, T>>>(n);
    k_deg_hist<<<nb_e, T>>>(edges, e);
    k_scan1<<<nb_sc, SCAN_B>>>(n);
    k_scan2<<<1, SCAN_B>>>(nb_sc);
    k_scan3<<<nb_n, T>>>(n, e + n);
    k_fill<<<nb_en, T>>>(edges, e, n);

    // --- 3 propagation hops: input -> A -> B -> out ---
    int warps_per_block = T / 32;
    int nb_spmm = (n + warps_per_block - 1) / warps_per_block;
    k_spmm<0, 1><<<nb_spmm, T>>>(h_local, nullptr, n);
    k_spmm<1, 2><<<nb_spmm, T>>>(nullptr, nullptr, n);
    k_spmm<2, 0><<<nb_spmm, T>>>(nullptr, (float*)d_out, n);
}

// round 6
// speedup vs baseline: 1.3195x; 1.3195x over previous
#include <cuda_runtime.h>
#include <cuda_fp16.h>
#include <cstdint>

// ---------------------------------------------------------------------------
// GlobalPropagation: 3-hop symmetric-normalized graph propagation (GCN-style)
//   H^{k+1}[i] = sum_{e: row_e==i} w_e * H^k[col_e],  w_e = dinv[row]*dinv[col]
//
// CSR built once per launch, then 3 atomic-free warp-per-row gather SpMM hops.
// Hops are L2-bandwidth-bound -> intermediates stored as fp16 (fp32 accum) to
// halve gather bytes. fp16 (10+1 mantissa bits) keeps rel_err ~3e-4 < 1e-3;
// bf16 (7+1 bits) measured 2.5e-3 and fails.
// ---------------------------------------------------------------------------

#define FEAT 128                 // feature dim
#define N_MAX 131072             // >= 100000 nodes
#define E_MAX 3400000            // >= 3200000 edges
#define CSR_MAX (E_MAX + N_MAX)  // edges + self loops
#define SCAN_B 1024

// Scratch (allocation-free rule: __device__ globals)
__device__ int   g_is64;
__device__ int   g_deg[N_MAX];
__device__ int   g_off[N_MAX + 1];
__device__ int   g_cur[N_MAX];
__device__ float g_dinv[N_MAX];
__device__ int2  g_cw[CSR_MAX];        // {col, bits(w)} -> one LDG.64 per edge
__device__ int   g_bsum[(N_MAX + SCAN_B - 1) / SCAN_B];
__device__ __half g_bufA[(size_t)N_MAX * FEAT];
__device__ __half g_bufB[(size_t)N_MAX * FEAT];

// ---------------------------------------------------------------------------
// 0) dtype sniffer: odd int32 words of first 8 elements all zero => int64
__global__ void k_detect(const unsigned int* __restrict__ p) {
    if (threadIdx.x == 0 && blockIdx.x == 0) {
        bool is64 = true;
        #pragma unroll
        for (int i = 1; i < 16; i += 2) is64 = is64 && (p[i] == 0u);
        g_is64 = is64 ? 1 : 0;
    }
}

__device__ __forceinline__ int load_edge(const void* base, long long idx) {
    if (g_is64) return (int)((const long long*)base)[idx];
    return ((const int*)base)[idx];
}

// 1) degree init (self loop contributes 1)
__global__ void k_deg_init(int n) {
    int i = blockIdx.x * blockDim.x + threadIdx.x;
    if (i < n) g_deg[i] = 1;
}

// 2) histogram of row indices (rows = elements [0, e))
__global__ void k_deg_hist(const void* __restrict__ edges, int e) {
    int i = blockIdx.x * blockDim.x + threadIdx.x;
    if (i < e) atomicAdd(&g_deg[load_edge(edges, i)], 1);
}

// 3) block-local exclusive scan of g_deg -> g_off, block totals -> g_bsum
__global__ void k_scan1(int n) {
    __shared__ int sh[SCAN_B];
    int i = blockIdx.x * SCAN_B + threadIdx.x;
    int v = (i < n) ? g_deg[i] : 0;
    sh[threadIdx.x] = v;
    __syncthreads();
    #pragma unroll
    for (int off = 1; off < SCAN_B; off <<= 1) {
        int t = (threadIdx.x >= off) ? sh[threadIdx.x - off] : 0;
        __syncthreads();
        sh[threadIdx.x] += t;
        __syncthreads();
    }
    if (i < n) g_off[i] = sh[threadIdx.x] - v;     // exclusive within block
    if (threadIdx.x == SCAN_B - 1) g_bsum[blockIdx.x] = sh[SCAN_B - 1];
}

// 4) exclusive scan of the (<=1024) block sums, single block
__global__ void k_scan2(int nb) {
    __shared__ int sh[SCAN_B];
    int v = (threadIdx.x < nb) ? g_bsum[threadIdx.x] : 0;
    sh[threadIdx.x] = v;
    __syncthreads();
    #pragma unroll
    for (int off = 1; off < SCAN_B; off <<= 1) {
        int t = (threadIdx.x >= off) ? sh[threadIdx.x - off] : 0;
        __syncthreads();
        sh[threadIdx.x] += t;
        __syncthreads();
    }
    if (threadIdx.x < nb) g_bsum[threadIdx.x] = sh[threadIdx.x] - v;
}

// 5) add block offsets, init cursors, dinv, and tail sentinel
__global__ void k_scan3(int n, int total) {
    int i = blockIdx.x * blockDim.x + threadIdx.x;
    if (i < n) {
        int o = g_off[i] + g_bsum[i / SCAN_B];
        g_off[i] = o;
        g_cur[i] = o;
        g_dinv[i] = rsqrtf((float)g_deg[i]);
    }
    if (i == 0) g_off[n] = total;
}

// 6) scatter edges + self loops into CSR slots ({col, w} packed)
__global__ void k_fill(const void* __restrict__ edges, int e, int n) {
    int i = blockIdx.x * blockDim.x + threadIdx.x;
    if (i < e) {
        int r = load_edge(edges, i);
        int c = load_edge(edges, (long long)e + i);
        int p = atomicAdd(&g_cur[r], 1);
        g_cw[p] = make_int2(c, __float_as_int(g_dinv[r] * g_dinv[c]));
    } else if (i < e + n) {
        int r = i - e;                 // self loop
        int p = atomicAdd(&g_cur[r], 1);
        float d = g_dinv[r];
        g_cw[p] = make_int2(r, __float_as_int(d * d));
    }
}

// 7) convert f32 input -> fp16 g_bufA (streaming)
__global__ void k_cvt(const float* __restrict__ in, int total2) {
    int i = blockIdx.x * blockDim.x + threadIdx.x;
    if (i < total2) {
        float2 v = ((const float2*)in)[i];
        ((__half2*)g_bufA)[i] = __floats2half2_rn(v.x, v.y);
    }
}

// 8) warp-per-row gather SpMM over fp16 source rows, fp32 accumulation.
//    Lane l covers features [4l, 4l+4): one uint2 (4 x fp16) load per neighbor.
//    SRC: 1 = g_bufA, 2 = g_bufB.  DST: 0 = f32 external out, 1/2 = fp16 bufs.
template <int SRC, int DST>
__global__ void __launch_bounds__(256)
k_spmm(float* __restrict__ Oext, int n) {
    const __half* __restrict__ Hin = (SRC == 1) ? g_bufA : g_bufB;

    int warp = (blockIdx.x * blockDim.x + threadIdx.x) >> 5;
    int lane = threadIdx.x & 31;
    if (warp >= n) return;

    int start = g_off[warp];
    int end   = g_off[warp + 1];

    float4 acc = make_float4(0.f, 0.f, 0.f, 0.f);

    for (int base = start; base < end; base += 32) {
        int idx = base + lane;
        int2 cw = make_int2(0, 0);
        if (idx < end) cw = g_cw[idx];
        int cnt = end - base;
        if (cnt > 32) cnt = 32;
        #pragma unroll 8
        for (int j = 0; j < cnt; ++j) {
            int   cj = __shfl_sync(0xffffffffu, cw.x, j);
            float wj = __int_as_float(__shfl_sync(0xffffffffu, cw.y, j));
            uint2 hv = __ldg(((const uint2*)(Hin + (size_t)cj * FEAT)) + lane);
            float2 f01 = __half22float2(*reinterpret_cast<__half2*>(&hv.x));
            float2 f23 = __half22float2(*reinterpret_cast<__half2*>(&hv.y));
            acc.x = fmaf(wj, f01.x, acc.x);
            acc.y = fmaf(wj, f01.y, acc.y);
            acc.z = fmaf(wj, f23.x, acc.z);
            acc.w = fmaf(wj, f23.y, acc.w);
        }
    }

    if (DST == 0) {
        ((float4*)(Oext + (size_t)warp * FEAT))[lane] = acc;
    } else {
        __half* Hout = (DST == 1) ? g_bufA : g_bufB;
        __half2 o0 = __floats2half2_rn(acc.x, acc.y);
        __half2 o1 = __floats2half2_rn(acc.z, acc.w);
        uint2 o;
        o.x = *reinterpret_cast<unsigned int*>(&o0);
        o.y = *reinterpret_cast<unsigned int*>(&o1);
        ((uint2*)(Hout + (size_t)warp * FEAT))[lane] = o;
    }
}

// ---------------------------------------------------------------------------
extern "C" void kernel_launch(void* const* d_in, const int* in_sizes, int n_in,
                              void* d_out, int out_size) {
    const float* h_local = (const float*)d_in[0];
    const void*  edges   = d_in[1];

    int n = in_sizes[0] / FEAT;     // number of nodes (100000)
    int e = in_sizes[1] / 2;        // number of edges (3200000)

    const int T = 256;
    int nb_n  = (n + T - 1) / T;
    int nb_e  = (e + T - 1) / T;
    int nb_en = (e + n + T - 1) / T;
    int nb_sc = (n + SCAN_B - 1) / SCAN_B;

    // --- dtype sniff + CSR build ---
    k_detect<<<1, 32>>>((const unsigned int*)edges);
    k_deg_init<<<nb_n, T>>>(n);
    k_deg_hist<<<nb_e, T>>>(edges, e);
    k_scan1<<<nb_sc, SCAN_B>>>(n);
    k_scan2<<<1, SCAN_B>>>(nb_sc);
    k_scan3<<<nb_n, T>>>(n, e + n);
    k_fill<<<nb_en, T>>>(edges, e, n);

    // --- input f32 -> fp16 bufA ---
    int total2 = n * FEAT / 2;
    k_cvt<<<(total2 + T - 1) / T, T>>>(h_local, total2);

    // --- 3 propagation hops: A -> B -> A -> f32 out ---
    int warps_per_block = T / 32;
    int nb_spmm = (n + warps_per_block - 1) / warps_per_block;
    k_spmm<1, 2><<<nb_spmm, T>>>(nullptr, n);
    k_spmm<2, 1><<<nb_spmm, T>>>(nullptr, n);
    k_spmm<1, 0><<<nb_spmm, T>>>((float*)d_out, n);
}

// round 8
// speedup vs baseline: 1.3373x; 1.0135x over previous
#include <cuda_runtime.h>
#include <cuda_fp16.h>
#include <cstdint>

// ---------------------------------------------------------------------------
// GlobalPropagation: 3-hop symmetric-normalized graph propagation (GCN-style)
//   H^{k+1}[i] = sum_{e: row_e==i} w_e * H^k[col_e],  w_e = dinv[row]*dinv[col]
//
// CSR built once per launch, then 3 atomic-free warp-per-row gather SpMM hops.
// Hops are AT the L2 (LTS) bandwidth roofline with fp16 intermediates
// (fp32 accumulation): 872 MB/hop -> ~79us/hop. fp16 keeps rel_err ~3e-4;
// bf16 measured 2.5e-3 (fails). This round: trimmed build path (fused detect,
// 2-edges-per-thread vectorized hist/fill, float4 cvt, __ldcs cw stream).
// ---------------------------------------------------------------------------

#define FEAT 128                 // feature dim
#define N_MAX 131072             // >= 100000 nodes
#define E_MAX 3400000            // >= 3200000 edges
#define CSR_MAX (E_MAX + N_MAX)  // edges + self loops
#define SCAN_B 1024

// Scratch (allocation-free rule: __device__ globals)
__device__ int   g_is64;
__device__ int   g_deg[N_MAX];
__device__ int   g_off[N_MAX + 1];
__device__ int   g_cur[N_MAX];
__device__ float g_dinv[N_MAX];
__device__ int2  g_cw[CSR_MAX];        // {col, bits(w)} -> one LDG.64 per edge
__device__ int   g_bsum[(N_MAX + SCAN_B - 1) / SCAN_B];
__device__ __half g_bufA[(size_t)N_MAX * FEAT];
__device__ __half g_bufB[(size_t)N_MAX * FEAT];

// ---------------------------------------------------------------------------
// 1) degree init (self loop contributes 1) + dtype sniff fused in thread 0.
//    int64 little-endian view of small values is [val,0,val,0,...], so
//    "odd int32 words of first 8 elements all zero" <=> int64.
__global__ void k_deg_init(const unsigned int* __restrict__ p, int n) {
    int i = blockIdx.x * blockDim.x + threadIdx.x;
    if (i < n) g_deg[i] = 1;
    if (i == 0) {
        bool is64 = true;
        #pragma unroll
        for (int k = 1; k < 16; k += 2) is64 = is64 && (p[k] == 0u);
        g_is64 = is64 ? 1 : 0;
    }
}

// 2) histogram of row indices (rows = elements [0, e)), 2 edges per thread
__global__ void k_deg_hist(const void* __restrict__ edges, int e) {
    int i = blockIdx.x * blockDim.x + threadIdx.x;
    int base = i * 2;
    if (base >= e) return;
    if (g_is64) {
        const long long* p = (const long long*)edges;
        if (base + 1 < e) {
            longlong2 v = ((const longlong2*)p)[i];
            atomicAdd(&g_deg[(int)v.x], 1);
            atomicAdd(&g_deg[(int)v.y], 1);
        } else {
            atomicAdd(&g_deg[(int)p[base]], 1);
        }
    } else {
        const int* p = (const int*)edges;
        if (base + 1 < e) {
            int2 v = ((const int2*)p)[i];
            atomicAdd(&g_deg[v.x], 1);
            atomicAdd(&g_deg[v.y], 1);
        } else {
            atomicAdd(&g_deg[p[base]], 1);
        }
    }
}

// 3) block-local exclusive scan of g_deg -> g_off, block totals -> g_bsum
__global__ void k_scan1(int n) {
    __shared__ int sh[SCAN_B];
    int i = blockIdx.x * SCAN_B + threadIdx.x;
    int v = (i < n) ? g_deg[i] : 0;
    sh[threadIdx.x] = v;
    __syncthreads();
    #pragma unroll
    for (int off = 1; off < SCAN_B; off <<= 1) {
        int t = (threadIdx.x >= off) ? sh[threadIdx.x - off] : 0;
        __syncthreads();
        sh[threadIdx.x] += t;
        __syncthreads();
    }
    if (i < n) g_off[i] = sh[threadIdx.x] - v;     // exclusive within block
    if (threadIdx.x == SCAN_B - 1) g_bsum[blockIdx.x] = sh[SCAN_B - 1];
}

// 4) exclusive scan of the (<=1024) block sums, single block
__global__ void k_scan2(int nb) {
    __shared__ int sh[SCAN_B];
    int v = (threadIdx.x < nb) ? g_bsum[threadIdx.x] : 0;
    sh[threadIdx.x] = v;
    __syncthreads();
    #pragma unroll
    for (int off = 1; off < SCAN_B; off <<= 1) {
        int t = (threadIdx.x >= off) ? sh[threadIdx.x - off] : 0;
        __syncthreads();
        sh[threadIdx.x] += t;
        __syncthreads();
    }
    if (threadIdx.x < nb) g_bsum[threadIdx.x] = sh[threadIdx.x] - v;
}

// 5) add block offsets, init cursors, dinv, and tail sentinel
__global__ void k_scan3(int n, int total) {
    int i = blockIdx.x * blockDim.x + threadIdx.x;
    if (i < n) {
        int o = g_off[i] + g_bsum[i / SCAN_B];
        g_off[i] = o;
        g_cur[i] = o;
        g_dinv[i] = rsqrtf((float)g_deg[i]);
    }
    if (i == 0) g_off[n] = total;
}

// 6) scatter edges + self loops into CSR slots ({col, w} packed),
//    2 edges per thread (vectorized row/col loads). rows=[0,e), cols=[e,2e).
__global__ void k_fill(const void* __restrict__ edges, int e, int n) {
    int i = blockIdx.x * blockDim.x + threadIdx.x;
    int eh = (e + 1) >> 1;               // threads covering edge pairs
    if (i < eh) {
        int r0, c0, r1 = -1, c1 = 0;
        int base = i * 2;
        if (g_is64) {
            const long long* p = (const long long*)edges;
            if (base + 1 < e) {
                longlong2 rv = ((const longlong2*)p)[i];
                longlong2 cv = ((const longlong2*)(p + e))[i];
                r0 = (int)rv.x; r1 = (int)rv.y;
                c0 = (int)cv.x; c1 = (int)cv.y;
            } else {
                r0 = (int)p[base]; c0 = (int)p[e + base];
            }
        } else {
            const int* p = (const int*)edges;
            if (base + 1 < e) {
                int2 rv = ((const int2*)p)[i];
                int2 cv = ((const int2*)(p + e))[i];
                r0 = rv.x; r1 = rv.y;
                c0 = cv.x; c1 = cv.y;
            } else {
                r0 = p[base]; c0 = p[e + base];
            }
        }
        int p0 = atomicAdd(&g_cur[r0], 1);
        g_cw[p0] = make_int2(c0, __float_as_int(g_dinv[r0] * g_dinv[c0]));
        if (r1 >= 0) {
            int p1 = atomicAdd(&g_cur[r1], 1);
            g_cw[p1] = make_int2(c1, __float_as_int(g_dinv[r1] * g_dinv[c1]));
        }
    } else if (i < eh + n) {
        int r = i - eh;                  // self loop
        int p = atomicAdd(&g_cur[r], 1);
        float d = g_dinv[r];
        g_cw[p] = make_int2(r, __float_as_int(d * d));
    }
}

// 7) convert f32 input -> fp16 g_bufA (streaming, float4 -> 4 x fp16)
__global__ void k_cvt(const float* __restrict__ in, int total4) {
    int i = blockIdx.x * blockDim.x + threadIdx.x;
    if (i < total4) {
        float4 v = ((const float4*)in)[i];
        __half2 a = __floats2half2_rn(v.x, v.y);
        __half2 b = __floats2half2_rn(v.z, v.w);
        uint2 o;
        o.x = *reinterpret_cast<unsigned int*>(&a);
        o.y = *reinterpret_cast<unsigned int*>(&b);
        ((uint2*)g_bufA)[i] = o;
    }
}

// 8) warp-per-row gather SpMM over fp16 source rows, fp32 accumulation.
//    Lane l covers features [4l, 4l+4): one uint2 (4 x fp16) load per neighbor.
//    SRC: 1 = g_bufA, 2 = g_bufB.  DST: 0 = f32 external out, 1/2 = fp16 bufs.
template <int SRC, int DST>
__global__ void __launch_bounds__(256)
k_spmm(float* __restrict__ Oext, int n) {
    const __half* __restrict__ Hin = (SRC == 1) ? g_bufA : g_bufB;

    int warp = (blockIdx.x * blockDim.x + threadIdx.x) >> 5;
    int lane = threadIdx.x & 31;
    if (warp >= n) return;

    int start = g_off[warp];
    int end   = g_off[warp + 1];

    float4 acc = make_float4(0.f, 0.f, 0.f, 0.f);

    for (int base = start; base < end; base += 32) {
        int idx = base + lane;
        int2 cw = make_int2(0, 0);
        if (idx < end) cw = __ldcs(&g_cw[idx]);   // streaming: protect H in L2
        int cnt = end - base;
        if (cnt > 32) cnt = 32;
        #pragma unroll 8
        for (int j = 0; j < cnt; ++j) {
            int   cj = __shfl_sync(0xffffffffu, cw.x, j);
            float wj = __int_as_float(__shfl_sync(0xffffffffu, cw.y, j));
            uint2 hv = __ldg(((const uint2*)(Hin + (size_t)cj * FEAT)) + lane);
            float2 f01 = __half22float2(*reinterpret_cast<__half2*>(&hv.x));
            float2 f23 = __half22float2(*reinterpret_cast<__half2*>(&hv.y));
            acc.x = fmaf(wj, f01.x, acc.x);
            acc.y = fmaf(wj, f01.y, acc.y);
            acc.z = fmaf(wj, f23.x, acc.z);
            acc.w = fmaf(wj, f23.y, acc.w);
        }
    }

    if (DST == 0) {
        ((float4*)(Oext + (size_t)warp * FEAT))[lane] = acc;
    } else {
        __half* Hout = (DST == 1) ? g_bufA : g_bufB;
        __half2 o0 = __floats2half2_rn(acc.x, acc.y);
        __half2 o1 = __floats2half2_rn(acc.z, acc.w);
        uint2 o;
        o.x = *reinterpret_cast<unsigned int*>(&o0);
        o.y = *reinterpret_cast<unsigned int*>(&o1);
        ((uint2*)(Hout + (size_t)warp * FEAT))[lane] = o;
    }
}

// ---------------------------------------------------------------------------
extern "C" void kernel_launch(void* const* d_in, const int* in_sizes, int n_in,
                              void* d_out, int out_size) {
    const float* h_local = (const float*)d_in[0];
    const void*  edges   = d_in[1];

    int n = in_sizes[0] / FEAT;     // number of nodes (100000)
    int e = in_sizes[1] / 2;        // number of edges (3200000)

    const int T = 256;
    int nb_n   = (n + T - 1) / T;
    int eh     = (e + 1) / 2;                        // edge pairs
    int nb_e2  = (eh + T - 1) / T;
    int nb_f   = (eh + n + T - 1) / T;
    int nb_sc  = (n + SCAN_B - 1) / SCAN_B;

    // --- CSR build (detect fused into deg_init) ---
    k_deg_init<<<nb_n, T>>>((const unsigned int*)edges, n);
    k_deg_hist<<<nb_e2, T>>>(edges, e);
    k_scan1<<<nb_sc, SCAN_B>>>(n);
    k_scan2<<<1, SCAN_B>>>(nb_sc);
    k_scan3<<<nb_n, T>>>(n, e + n);
    k_fill<<<nb_f, T>>>(edges, e, n);

    // --- input f32 -> fp16 bufA ---
    int total4 = n * FEAT / 4;
    k_cvt<<<(total4 + T - 1) / T, T>>>(h_local, total4);

    // --- 3 propagation hops: A -> B -> A -> f32 out ---
    int warps_per_block = T / 32;
    int nb_spmm = (n + warps_per_block - 1) / warps_per_block;
    k_spmm<1, 2><<<nb_spmm, T>>>(nullptr, n);
    k_spmm<2, 1><<<nb_spmm, T>>>(nullptr, n);
    k_spmm<1, 0><<<nb_spmm, T>>>((float*)d_out, n);
}

// round 9
// speedup vs baseline: 1.5142x; 1.1323x over previous
#include <cuda_runtime.h>
#include <cuda_fp16.h>
#include <cstdint>

// ---------------------------------------------------------------------------
// GlobalPropagation: 3-hop symmetric-normalized graph propagation (GCN-style)
//   H^{k+1}[i] = sum_{e: row_e==i} dinv_i*dinv_j*H^k[j]  (+ self loop)
//
// Scaled-H formulation: store Hs = dinv .* H. Then
//   S[r]   = sum_{(r,c)} Hs[c] + Hs[r]
//   H'[r]  = dinv_r * S[r]          (final hop, f32 out)
//   Hs'[r] = dinv_r^2 * S[r]        (intermediate hops, fp16)
// => CSR needs ONLY col indices (4 B/edge), no per-edge weight.
//
// CSR built per launch (counting sort), 3 atomic-free warp-per-row gather
// hops at the L2 bandwidth roofline (fp16 storage, fp32 accum).
// Launch count minimized: scan2 fused into scan3, cvt fused into fill.
// ---------------------------------------------------------------------------

#define FEAT 128                 // feature dim
#define N_MAX 131072             // >= 100000 nodes
#define E_MAX 3400000            // >= 3200000 edges
#define CSR_MAX (E_MAX + N_MAX)  // edges + self loops
#define SCAN_B 1024

// Scratch (allocation-free rule: __device__ globals)
__device__ int   g_is64;
__device__ int   g_deg[N_MAX];
__device__ int   g_off[N_MAX + 1];
__device__ int   g_cur[N_MAX];
__device__ float g_dinv[N_MAX];
__device__ int   g_col[CSR_MAX];       // col-only CSR (4 B/edge)
__device__ int   g_bsum[(N_MAX + SCAN_B - 1) / SCAN_B];
__device__ __half g_bufA[(size_t)N_MAX * FEAT];
__device__ __half g_bufB[(size_t)N_MAX * FEAT];

// ---------------------------------------------------------------------------
// 1) degree init (self loop contributes 1) + dtype sniff fused in thread 0.
//    int64 little-endian view of small values is [val,0,val,0,...], so
//    "odd int32 words of first 8 elements all zero" <=> int64.
__global__ void k_deg_init(const unsigned int* __restrict__ p, int n) {
    int i = blockIdx.x * blockDim.x + threadIdx.x;
    if (i < n) g_deg[i] = 1;
    if (i == 0) {
        bool is64 = true;
        #pragma unroll
        for (int k = 1; k < 16; k += 2) is64 = is64 && (p[k] == 0u);
        g_is64 = is64 ? 1 : 0;
    }
}

// 2) histogram of row indices (rows = elements [0, e)), 2 edges per thread
__global__ void k_deg_hist(const void* __restrict__ edges, int e) {
    int i = blockIdx.x * blockDim.x + threadIdx.x;
    int base = i * 2;
    if (base >= e) return;
    if (g_is64) {
        const long long* p = (const long long*)edges;
        if (base + 1 < e) {
            longlong2 v = ((const longlong2*)p)[i];
            atomicAdd(&g_deg[(int)v.x], 1);
            atomicAdd(&g_deg[(int)v.y], 1);
        } else {
            atomicAdd(&g_deg[(int)p[base]], 1);
        }
    } else {
        const int* p = (const int*)edges;
        if (base + 1 < e) {
            int2 v = ((const int2*)p)[i];
            atomicAdd(&g_deg[v.x], 1);
            atomicAdd(&g_deg[v.y], 1);
        } else {
            atomicAdd(&g_deg[p[base]], 1);
        }
    }
}

// 3) block-local exclusive scan of g_deg -> g_off, block totals -> g_bsum
__global__ void k_scan1(int n) {
    __shared__ int sh[SCAN_B];
    int i = blockIdx.x * SCAN_B + threadIdx.x;
    int v = (i < n) ? g_deg[i] : 0;
    sh[threadIdx.x] = v;
    __syncthreads();
    #pragma unroll
    for (int off = 1; off < SCAN_B; off <<= 1) {
        int t = (threadIdx.x >= off) ? sh[threadIdx.x - off] : 0;
        __syncthreads();
        sh[threadIdx.x] += t;
        __syncthreads();
    }
    if (i < n) g_off[i] = sh[threadIdx.x] - v;     // exclusive within block
    if (threadIdx.x == SCAN_B - 1) g_bsum[blockIdx.x] = sh[SCAN_B - 1];
}

// 4) scan3 with fused block-sum prefix (was scan2): warp 0 of each block
//    reduces g_bsum[0..blockIdx) (<=98 values), then applies offsets,
//    inits cursors, dinv, tail sentinel.
__global__ void k_scan3(int n, int total) {
    __shared__ int base_sh;
    if (threadIdx.x < 32) {
        int acc = 0;
        for (int k = threadIdx.x; k < blockIdx.x; k += 32) acc += g_bsum[k];
        #pragma unroll
        for (int off = 16; off > 0; off >>= 1)
            acc += __shfl_down_sync(0xffffffffu, acc, off);
        if (threadIdx.x == 0) base_sh = acc;
    }
    __syncthreads();
    int i = blockIdx.x * blockDim.x + threadIdx.x;
    // NOTE: this kernel must be launched with blockDim == SCAN_B so that
    // block b covers exactly scan1's block b (same bsum granularity).
    if (i < n) {
        int o = g_off[i] + base_sh;
        g_off[i] = o;
        g_cur[i] = o;
        g_dinv[i] = rsqrtf((float)g_deg[i]);
    }
    if (i == 0) g_off[n] = total;
}

// 5) fill (col-only CSR, 2 edges/thread) + self loops + FUSED cvt:
//    Hs0 = dinv .* H  (f32 -> fp16, float4 granularity).
//    Thread ranges: [0,eh) edge pairs | [eh,eh+n) self loops |
//                   [eh+n, eh+n+total4) cvt quads.
__global__ void k_fill(const void* __restrict__ edges,
                       const float* __restrict__ hin,
                       int e, int n, int total4) {
    int i = blockIdx.x * blockDim.x + threadIdx.x;
    int eh = (e + 1) >> 1;
    if (i < eh) {
        int r0, c0, r1 = -1, c1 = 0;
        int base = i * 2;
        if (g_is64) {
            const long long* p = (const long long*)edges;
            if (base + 1 < e) {
                longlong2 rv = ((const longlong2*)p)[i];
                longlong2 cv = ((const longlong2*)(p + e))[i];
                r0 = (int)rv.x; r1 = (int)rv.y;
                c0 = (int)cv.x; c1 = (int)cv.y;
            } else {
                r0 = (int)p[base]; c0 = (int)p[e + base];
            }
        } else {
            const int* p = (const int*)edges;
            if (base + 1 < e) {
                int2 rv = ((const int2*)p)[i];
                int2 cv = ((const int2*)(p + e))[i];
                r0 = rv.x; r1 = rv.y;
                c0 = cv.x; c1 = cv.y;
            } else {
                r0 = p[base]; c0 = p[e + base];
            }
        }
        g_col[atomicAdd(&g_cur[r0], 1)] = c0;
        if (r1 >= 0) g_col[atomicAdd(&g_cur[r1], 1)] = c1;
    } else if (i < eh + n) {
        int r = i - eh;                  // self loop
        g_col[atomicAdd(&g_cur[r], 1)] = r;
    } else if (i < eh + n + total4) {
        int q = i - (eh + n);            // cvt: one float4 -> 4 fp16
        int node = q >> 5;               // FEAT/4 = 32 quads per node
        float d = g_dinv[node];
        float4 v = ((const float4*)hin)[q];
        __half2 a = __floats2half2_rn(v.x * d, v.y * d);
        __half2 b = __floats2half2_rn(v.z * d, v.w * d);
        uint2 o;
        o.x = *reinterpret_cast<unsigned int*>(&a);
        o.y = *reinterpret_cast<unsigned int*>(&b);
        ((uint2*)g_bufA)[q] = o;
    }
}

// 6) warp-per-row gather SpMM over fp16 scaled rows, fp32 accumulation.
//    Lane l covers features [4l,4l+4): one uint2 (4 x fp16) per neighbor.
//    Epilogue applies dinv_r (final f32 out) or dinv_r^2 (fp16 intermediate).
//    SRC: 1 = g_bufA, 2 = g_bufB.  DST: 0 = f32 external out, 1/2 = fp16 bufs.
template <int SRC, int DST>
__global__ void __launch_bounds__(256)
k_spmm(float* __restrict__ Oext, int n) {
    const __half* __restrict__ Hin = (SRC == 1) ? g_bufA : g_bufB;

    int warp = (blockIdx.x * blockDim.x + threadIdx.x) >> 5;
    int lane = threadIdx.x & 31;
    if (warp >= n) return;

    int start = g_off[warp];
    int end   = g_off[warp + 1];
    float dr  = g_dinv[warp];            // broadcast load

    float4 acc = make_float4(0.f, 0.f, 0.f, 0.f);

    for (int base = start; base < end; base += 32) {
        int idx = base + lane;
        int c = 0;
        if (idx < end) c = __ldcs(&g_col[idx]);   // streaming: protect Hs in L2
        int cnt = end - base;
        if (cnt > 32) cnt = 32;
        #pragma unroll 8
        for (int j = 0; j < cnt; ++j) {
            int cj = __shfl_sync(0xffffffffu, c, j);
            uint2 hv = __ldg(((const uint2*)(Hin + (size_t)cj * FEAT)) + lane);
            float2 f01 = __half22float2(*reinterpret_cast<__half2*>(&hv.x));
            float2 f23 = __half22float2(*reinterpret_cast<__half2*>(&hv.y));
            acc.x += f01.x;
            acc.y += f01.y;
            acc.z += f23.x;
            acc.w += f23.y;
        }
    }

    if (DST == 0) {
        // final hop: H3 = dinv_r * S
        acc.x *= dr; acc.y *= dr; acc.z *= dr; acc.w *= dr;
        ((float4*)(Oext + (size_t)warp * FEAT))[lane] = acc;
    } else {
        // intermediate hop: Hs' = dinv_r^2 * S
        float s = dr * dr;
        __half* Hout = (DST == 1) ? g_bufA : g_bufB;
        __half2 o0 = __floats2half2_rn(acc.x * s, acc.y * s);
        __half2 o1 = __floats2half2_rn(acc.z * s, acc.w * s);
        uint2 o;
        o.x = *reinterpret_cast<unsigned int*>(&o0);
        o.y = *reinterpret_cast<unsigned int*>(&o1);
        ((uint2*)(Hout + (size_t)warp * FEAT))[lane] = o;
    }
}

// ---------------------------------------------------------------------------
extern "C" void kernel_launch(void* const* d_in, const int* in_sizes, int n_in,
                              void* d_out, int out_size) {
    const float* h_local = (const float*)d_in[0];
    const void*  edges   = d_in[1];

    int n = in_sizes[0] / FEAT;     // number of nodes (100000)
    int e = in_sizes[1] / 2;        // number of edges (3200000)

    const int T = 256;
    int nb_n   = (n + T - 1) / T;
    int eh     = (e + 1) / 2;                        // edge pairs
    int nb_e2  = (eh + T - 1) / T;
    int total4 = n * FEAT / 4;
    int nb_f   = (eh + n + total4 + T - 1) / T;
    int nb_sc  = (n + SCAN_B - 1) / SCAN_B;

    // --- CSR build (scan2 fused into scan3; cvt fused into fill) ---
    k_deg_init<<<nb_n, T>>>((const unsigned int*)edges, n);
    k_deg_hist<<<nb_e2, T>>>(edges, e);
    k_scan1<<<nb_sc, SCAN_B>>>(n);
    k_scan3<<<nb_sc, SCAN_B>>>(n, e + n);
    k_fill<<<nb_f, T>>>(edges, h_local, e, n, total4);

    // --- 3 propagation hops: A -> B -> A -> f32 out ---
    int warps_per_block = T / 32;
    int nb_spmm = (n + warps_per_block - 1) / warps_per_block;
    k_spmm<1, 2><<<nb_spmm, T>>>(nullptr, n);
    k_spmm<2, 1><<<nb_spmm, T>>>(nullptr, n);
    k_spmm<1, 0><<<nb_spmm, T>>>((float*)d_out, n);
}